// round 4
// baseline (speedup 1.0000x reference)
#include <cuda_runtime.h>
#include <math.h>

#define B  32
#define L  128
#define H  512
#define EN 256
#define ET 512
#define VN 300
#define VO 10053
#define EOFT 9999
#define G4 2048
#define KG 1536
#define LDZ 10080
#define PADW 36

// ------------- static device scratch (no allocations) -------------
__device__ float g_wihP[(EN + ET) * G4];   // [k][u*4+g]
__device__ float g_whhP[H * G4];           // [k][u*4+g]
__device__ float g_biasP[G4];              // permuted b_ih+b_hh
__device__ float g_wgT[KG * LDZ];          // [k][j], cols >= VO zeroed
__device__ float g_TN[VN * G4];            // embN @ w_ihN^T (permuted cols)
__device__ float g_GX[B * L * G4];         // hoisted input-side gates
__device__ float g_h[2][B * H];
__device__ float g_c[2][B * H];
__device__ float g_hs[B * L * H];
__device__ float g_z[B * LDZ];
__device__ float g_tl[B * L];

// ------------- prep: permute w_ih / w_hh / bias -------------
__global__ void kPrep(const float* __restrict__ w_ih, const float* __restrict__ w_hh,
                      const float* __restrict__ b_ih, const float* __restrict__ b_hh) {
    const int n1 = G4 * (EN + ET), n2 = G4 * H;
    for (int i = blockIdx.x * blockDim.x + threadIdx.x; i < n1 + n2 + G4;
         i += gridDim.x * blockDim.x) {
        if (i < n1) {
            int j = i / (EN + ET), k = i % (EN + ET);
            g_wihP[k * G4 + (j & 511) * 4 + (j >> 9)] = w_ih[i];
        } else if (i < n1 + n2) {
            int e = i - n1;
            int j = e / H, k = e % H;
            g_whhP[k * G4 + (j & 511) * 4 + (j >> 9)] = w_hh[e];
        } else {
            int j = i - n1 - n2;
            g_biasP[(j & 511) * 4 + (j >> 9)] = b_ih[j] + b_hh[j];
        }
    }
}

// ------------- prep: transpose Wg_w [VO][KG] -> g_wgT[k][LDZ] -------------
__global__ void kPrepWg(const float* __restrict__ Wg_w) {
    __shared__ float tile[32][33];
    int j0 = blockIdx.x * 32, k0 = blockIdx.y * 32;
    int tx = threadIdx.x, ty = threadIdx.y;  // 32 x 8
#pragma unroll
    for (int i = 0; i < 32; i += 8) {
        int j = j0 + ty + i, k = k0 + tx;
        tile[ty + i][tx] = (j < VO) ? Wg_w[(size_t)j * KG + k] : 0.f;
    }
    __syncthreads();
#pragma unroll
    for (int i = 0; i < 32; i += 8) {
        int k = k0 + ty + i, j = j0 + tx;
        g_wgT[(size_t)k * LDZ + j] = tile[tx][ty + i];
    }
}

// ------------- prep: TN[v][j'] = embN[v] . w_ihN[j'] -------------
__global__ void __launch_bounds__(256) kTN(const float* __restrict__ embN) {
    __shared__ float se[8][EN];
    int t = threadIdx.x;
    int j = blockIdx.x * 256 + t;
    int v0 = blockIdx.y * 8;
    for (int f = t; f < 8 * EN; f += 256) {
        int vv = f >> 8, k = f & 255;
        int v = v0 + vv;
        se[vv][k] = (v < VN) ? embN[v * EN + k] : 0.f;
    }
    __syncthreads();
    float acc[8];
#pragma unroll
    for (int i = 0; i < 8; i++) acc[i] = 0.f;
    for (int k = 0; k < EN; k++) {
        float w = g_wihP[k * G4 + j];
#pragma unroll
        for (int vv = 0; vv < 8; vv++) acc[vv] += se[vv][k] * w;
    }
#pragma unroll
    for (int vv = 0; vv < 8; vv++) {
        int v = v0 + vv;
        if (v < VN) g_TN[v * G4 + j] = acc[vv];
    }
}

// ------------- prep: GX[(it*B+b)][j'] = TN[n] + embT[t].w_ihT + bias ------
__global__ void __launch_bounds__(256) kGX(const float* __restrict__ embT,
                                           const int* __restrict__ nT,
                                           const int* __restrict__ tT) {
    __shared__ float sx[64][PADW];
    __shared__ int sti[32], sni[32];
    int t = threadIdx.x;
    int jj = t & 63, rg = t >> 6;
    int it = blockIdx.y;
    int j = blockIdx.x * 64 + jj;
    if (t < 32) {
        sti[t] = (it == 0) ? 0 : tT[t * L + it - 1];
        sni[t] = (it == 0) ? 0 : nT[t * L + it - 1];
    }
    __syncthreads();
    float bs = g_biasP[j];
    float acc[8];
#pragma unroll
    for (int i = 0; i < 8; i++) acc[i] = g_TN[sni[rg * 8 + i] * G4 + j] + bs;
    for (int kc = 0; kc < ET; kc += 64) {
        __syncthreads();
        for (int f = t; f < 512; f += 256) {
            int rr = f >> 4, ks = f & 15;
            const float4 v = *(const float4*)&embT[(size_t)sti[rr] * ET + kc + ks * 4];
            sx[ks * 4 + 0][rr] = v.x; sx[ks * 4 + 1][rr] = v.y;
            sx[ks * 4 + 2][rr] = v.z; sx[ks * 4 + 3][rr] = v.w;
        }
        __syncthreads();
#pragma unroll 8
        for (int kk = 0; kk < 64; kk++) {
            float w = g_wihP[(EN + kc + kk) * G4 + j];
            float4 xa = *(float4*)&sx[kk][rg * 8];
            float4 xb = *(float4*)&sx[kk][rg * 8 + 4];
            acc[0] += xa.x * w; acc[1] += xa.y * w;
            acc[2] += xa.z * w; acc[3] += xa.w * w;
            acc[4] += xb.x * w; acc[5] += xb.y * w;
            acc[6] += xb.z * w; acc[7] += xb.w * w;
        }
    }
#pragma unroll
    for (int i = 0; i < 8; i++)
        g_GX[(size_t)(it * B + rg * 8 + i) * G4 + j] = acc[i];
}

// ------------- init h0/c0 -------------
__global__ void kInit() {
    int i = blockIdx.x * blockDim.x + threadIdx.x;
    if (i < B * H) { g_h[0][i] = 0.f; g_c[0][i] = 0.f; }
}

// ------------- per-step S1: recurrent gates + cell update -------------
__global__ void __launch_bounds__(256) kS1(int it) {
    int p = it & 1, cur = p ^ 1;
    __shared__ float sh[64][PADW];
    __shared__ float gsm[16][32];
    int t = threadIdx.x;
    int jj = t & 15, bg = t >> 4;   // 16 cols x 16 b-groups (2 b each)
    int u0 = blockIdx.x * 4;
    int jcol = u0 * 4 + jj;
    float a0 = 0.f, a1 = 0.f;
    for (int kc = 0; kc < H; kc += 64) {
        __syncthreads();
        for (int f = t; f < 512; f += 256) {
            int rr = f >> 4, ks = f & 15;
            const float4 v = *(const float4*)&g_h[p][rr * H + kc + ks * 4];
            sh[ks * 4 + 0][rr] = v.x; sh[ks * 4 + 1][rr] = v.y;
            sh[ks * 4 + 2][rr] = v.z; sh[ks * 4 + 3][rr] = v.w;
        }
        __syncthreads();
#pragma unroll 8
        for (int kk = 0; kk < 64; kk++) {
            float w = g_whhP[(kc + kk) * G4 + jcol];
            float2 x = *(float2*)&sh[kk][bg * 2];
            a0 += x.x * w; a1 += x.y * w;
        }
    }
    int r = it * B;
    gsm[jj][bg * 2 + 0] = a0 + g_GX[(size_t)(r + bg * 2 + 0) * G4 + jcol];
    gsm[jj][bg * 2 + 1] = a1 + g_GX[(size_t)(r + bg * 2 + 1) * G4 + jcol];
    __syncthreads();
    if (t < 128) {
        int b = t & 31, ul = t >> 5;
        float ig = gsm[ul * 4 + 0][b];
        float fg = gsm[ul * 4 + 1][b];
        float gg = gsm[ul * 4 + 2][b];
        float og = gsm[ul * 4 + 3][b];
        int u = u0 + ul;
        float cp = g_c[p][b * H + u];
        float si = 1.f / (1.f + expf(-ig));
        float sf = 1.f / (1.f + expf(-fg));
        float so = 1.f / (1.f + expf(-og));
        float cn = sf * cp + si * tanhf(gg);
        float hn = so * tanhf(cn);
        g_c[cur][b * H + u] = cn;
        g_h[cur][b * H + u] = hn;
        g_hs[(size_t)(b * L + it) * H + u] = hn;
    }
}

// ------------- per-step S3: z = [h,c,h_parent] @ Wg^T + b -------------
__global__ void __launch_bounds__(256) kS3(int it, const int* __restrict__ pT,
                                           const float* __restrict__ Wg_b) {
    int cur = (it & 1) ^ 1;
    __shared__ float sx[64][PADW];
    __shared__ int spar[32];
    int t = threadIdx.x;
    int jj = t & 31, bg = t >> 5;   // 32 cols x 8 b-groups (4 b each)
    int j = blockIdx.x * 32 + jj;
    if (t < 32) {
        int par = (it == 0) ? 0 : pT[t * L + it - 1];
        spar[t] = (it > 0 && par < it) ? par : -1;
    }
    float acc[4] = {0.f, 0.f, 0.f, 0.f};
    for (int kc = 0; kc < KG; kc += 64) {
        __syncthreads();
        for (int f = t; f < 512; f += 256) {
            int rr = f >> 4, ks = f & 15;
            int k = kc + ks * 4;
            float4 v;
            if (k < H) v = *(const float4*)&g_h[cur][rr * H + k];
            else if (k < 2 * H) v = *(const float4*)&g_c[cur][rr * H + k - H];
            else {
                int par = spar[rr];
                if (par >= 0) v = *(const float4*)&g_hs[(size_t)(rr * L + par) * H + k - 2 * H];
                else v = make_float4(0.f, 0.f, 0.f, 0.f);
            }
            sx[ks * 4 + 0][rr] = v.x; sx[ks * 4 + 1][rr] = v.y;
            sx[ks * 4 + 2][rr] = v.z; sx[ks * 4 + 3][rr] = v.w;
        }
        __syncthreads();
#pragma unroll 8
        for (int kk = 0; kk < 64; kk++) {
            float w = __ldg(&g_wgT[(size_t)(kc + kk) * LDZ + j]);
            float4 x = *(float4*)&sx[kk][bg * 4];
            acc[0] += x.x * w; acc[1] += x.y * w;
            acc[2] += x.z * w; acc[3] += x.w * w;
        }
    }
    if (j < VO) {
        float bb = Wg_b[j];
#pragma unroll
        for (int i = 0; i < 4; i++)
            g_z[(bg * 4 + i) * LDZ + j] = acc[i] + bb;
    }
}

// ------------- per-step S4: s_t, reductions over z, tl + topi -------------
__global__ void __launch_bounds__(256) kS4(int it, const int* __restrict__ tT,
                                           const float* __restrict__ Ws_w,
                                           const float* __restrict__ Ws_b,
                                           float* __restrict__ out, int out_size) {
    int b = blockIdx.x, t = threadIdx.x;
    int cur = (it & 1) ^ 1;
    __shared__ float rf[256];
    __shared__ int ri[256];
    __shared__ float sS, sMx, sSz;
    __shared__ int sMi;

    // s_t = sigmoid([h,c] . Ws_w + Ws_b)
    float sp = 0.f;
    for (int k = t; k < 2 * H; k += 256)
        sp += ((k < H) ? g_h[cur][b * H + k] : g_c[cur][b * H + k - H]) * Ws_w[k];
    rf[t] = sp; __syncthreads();
    for (int s = 128; s; s >>= 1) { if (t < s) rf[t] += rf[t + s]; __syncthreads(); }
    if (t == 0) sS = 1.f / (1.f + expf(-(rf[0] + Ws_b[0])));
    __syncthreads();

    const float* zr = &g_z[b * LDZ];
    // pass 1: sum, max, argmax
    float mx = -3.4e38f; int mi = 0; float sz = 0.f;
    for (int j = t; j < VO; j += 256) {
        float v = zr[j];
        sz += v;
        if (v > mx) { mx = v; mi = j; }
    }
    rf[t] = sz; __syncthreads();
    for (int s = 128; s; s >>= 1) { if (t < s) rf[t] += rf[t + s]; __syncthreads(); }
    if (t == 0) sSz = rf[0];
    __syncthreads();
    rf[t] = mx; ri[t] = mi; __syncthreads();
    for (int s = 128; s; s >>= 1) {
        if (t < s) {
            float v2 = rf[t + s]; int i2 = ri[t + s];
            if (v2 > rf[t] || (v2 == rf[t] && i2 < ri[t])) { rf[t] = v2; ri[t] = i2; }
        }
        __syncthreads();
    }
    if (t == 0) { sMx = rf[0]; sMi = ri[0]; }
    __syncthreads();
    // pass 2: sum exp(z - max)
    float mxv = sMx;
    float se = 0.f;
    for (int j = t; j < VO; j += 256) se += expf(zr[j] - mxv);
    rf[t] = se; __syncthreads();
    for (int s = 128; s; s >>= 1) { if (t < s) rf[t] += rf[t + s]; __syncthreads(); }
    if (t == 0) {
        float lse = mxv + logf(rf[0]);
        float s = sS;
        int tc = tT[b * L + it];
        float tl;
        if (tc == EOFT) tl = 0.f;
        else {
            float out_tc  = s * (zr[tc]   - lse);
            float out_eof = s * (zr[EOFT] - lse);
            float Ssum    = s * (sSz - (float)VO * lse);
            const float smv = 0.1f / (float)(VO - 2);
            tl = 0.1f * logf(smv) + 0.9f * logf(0.9f)
               - smv * (Ssum - out_eof - out_tc) - 0.9f * out_tc;
        }
        g_tl[it * B + b] = tl;
        int oi = 1 + b * L + it;
        if (oi < out_size) out[oi] = (float)sMi;
    }
}

// ------------- final: sum tl, zero any tail -------------
__global__ void kFinal(float* __restrict__ out, int out_size) {
    __shared__ float rf[256];
    int t = threadIdx.x;
    float s = 0.f;
    for (int i = t; i < B * L; i += 256) s += g_tl[i];
    rf[t] = s; __syncthreads();
    for (int k = 128; k; k >>= 1) { if (t < k) rf[t] += rf[t + k]; __syncthreads(); }
    if (t == 0 && out_size > 0) out[0] = rf[0];
    for (int i = 1 + B * L + t; i < out_size; i += 256) out[i] = 0.f;
}

extern "C" void kernel_launch(void* const* d_in, const int* in_sizes, int n_in,
                              void* d_out, int out_size) {
    const int*   nT   = (const int*)d_in[0];
    const int*   tT   = (const int*)d_in[1];
    const int*   pT   = (const int*)d_in[2];
    const float* embN = (const float*)d_in[3];
    const float* embT = (const float*)d_in[4];
    const float* w_ih = (const float*)d_in[5];
    const float* w_hh = (const float*)d_in[6];
    const float* b_ih = (const float*)d_in[7];
    const float* b_hh = (const float*)d_in[8];
    // d_in[9..12] (Wh_w, Wh_b, v_w, v_b) are dead code — attention branch never wins.
    const float* Wg_w = (const float*)d_in[13];
    const float* Wg_b = (const float*)d_in[14];
    const float* Ws_w = (const float*)d_in[15];
    const float* Ws_b = (const float*)d_in[16];
    float* out = (float*)d_out;

    kPrep<<<1024, 256>>>(w_ih, w_hh, b_ih, b_hh);
    kPrepWg<<<dim3(LDZ / 32, KG / 32), dim3(32, 8)>>>(Wg_w);
    kTN<<<dim3(G4 / 256, (VN + 7) / 8), 256>>>(embN);
    kGX<<<dim3(G4 / 64, L), 256>>>(embT, nT, tT);
    kInit<<<(B * H + 255) / 256, 256>>>();

    for (int it = 0; it < L; ++it) {
        kS1<<<H / 4, 256>>>(it);
        kS3<<<LDZ / 32, 256>>>(it, pT, Wg_b);
        kS4<<<B, 256>>>(it, tT, Ws_w, Ws_b, out, out_size);
    }
    kFinal<<<1, 256>>>(out, out_size);
}